// round 9
// baseline (speedup 1.0000x reference)
#include <cuda_runtime.h>
#include <stdint.h>

#define BB    32
#define NBOX  8192
#define MGT   256
#define NP    8448        // NBOX + MGT
#define NSAMP 512
#define NFG   128
#define KBIN  256
#define KCAP  4096
#define LCAP  256
#define THRESH (1u << 20)            // keep negatives with inv_m < 2^20 (r > 0.875)
#define MASK37 ((1ull << 37) - 1)

// scratch (device globals -- no allocation allowed; zero-initialized at load,
// and kernel 2 re-zeroes g_cnt after consuming it -> graph-replay safe)
__device__ unsigned long long g_sel[BB * KCAP];
__device__ unsigned int       g_cnt[BB];

__device__ __forceinline__ uint32_t rotl32(uint32_t x, int d) {
    return (x << d) | (x >> (32 - d));
}

// JAX *partitionable* threefry, key = (0, 42). bits(p) = x0 ^ x1 of
// threefry2x32((0,42), (0, p))
__device__ __forceinline__ uint32_t threefry_bits(uint32_t p) {
    const uint32_t ks0 = 0u, ks1 = 42u, ks2 = 0x1BD11BF0u;  // 0x1BD11BDA ^ 0 ^ 42
    uint32_t x0 = 0u + ks0;
    uint32_t x1 = p + ks1;
#define TF_R(r) { x0 += x1; x1 = rotl32(x1, (r)); x1 ^= x0; }
    TF_R(13) TF_R(15) TF_R(26) TF_R(6)   x0 += ks1; x1 += ks2 + 1u;
    TF_R(17) TF_R(29) TF_R(16) TF_R(24)  x0 += ks2; x1 += ks0 + 2u;
    TF_R(13) TF_R(15) TF_R(26) TF_R(6)   x0 += ks0; x1 += ks1 + 3u;
    TF_R(17) TF_R(29) TF_R(16) TF_R(24)  x0 += ks1; x1 += ks2 + 4u;
    TF_R(13) TF_R(15) TF_R(26) TF_R(6)   x0 += ks2; x1 += ks0 + 5u;
#undef TF_R
    return x0 ^ x1;
}

// packed survivor word: [0:14) idx | [14:37) inv_m | bit37 pos | [38:46) mi
__device__ __forceinline__ void emit(int b, int i, bool pos, int mi) {
    uint32_t m = threefry_bits((uint32_t)(b * NP + i)) >> 9;
    uint32_t invm = 0x7FFFFFu - m;     // asc == r desc
    if (pos || invm < THRESH) {
        unsigned long long w = ((unsigned long long)(unsigned)mi << 38)
            | ((unsigned long long)(pos ? 1u : 0u) << 37)
            | ((unsigned long long)invm << 14) | (unsigned)i;
        unsigned j = atomicAdd(&g_cnt[b], 1u);
        if (j < KCAP) g_sel[b * KCAP + j] = w;
    }
}

// Branchless running-argmax of iou=inter/uni via cross-multiplication.
// EXACTLY equivalent to the guarded form: first overlapping gt always wins
// (inter*1 > 0*uni), strict > keeps earlier index on ties, bi>0 <=> overlap.
template <int NB>
__device__ __forceinline__ void iou_loop(
    int nv, const float4* __restrict__ sg, const float* __restrict__ sga,
    const float4* B, const float* ab, float* bi, float* bu, int* mi)
{
#pragma unroll 2
    for (int g = 0; g < nv; ++g) {
        float4 gb = sg[g];
        float  ga = sga[g];
#pragma unroll
        for (int k = 0; k < NB; ++k) {
            float dy = fminf(B[k].z, gb.z) - fmaxf(B[k].x, gb.x);
            float dx = fminf(B[k].w, gb.w) - fmaxf(B[k].y, gb.y);
            float inter = fmaxf(dy, 0.0f) * fmaxf(dx, 0.0f);
            float uni   = (ab[k] + ga) - inter;
            bool upd = (inter * bu[k] > bi[k] * uni);   // same compare as passing rounds
            bi[k] = upd ? inter : bi[k];
            bu[k] = upd ? uni   : bu[k];
            mi[k] = upd ? g     : mi[k];
        }
    }
}

// ---------------------------------------------------------------------------
// Kernel 1: max-IoU matching, 4 boxes/thread (4 independent dep-chains),
// valid-gt prefix; emits prefiltered survivors (compacted).
// grid (32, 9): x = image; y slices 0..7 -> 1024 proposals each; 8 -> gts.
// ---------------------------------------------------------------------------
__global__ __launch_bounds__(256)
void roi_match_kernel(const float* __restrict__ boxes,
                      const float* __restrict__ gt_boxes) {
    __shared__ float4 sg[MGT];
    __shared__ float  sga[MGT];

    const int b = blockIdx.x;
    const int s = blockIdx.y;
    const int t = threadIdx.x;
    int nv;
    {
        float4 g = ((const float4*)gt_boxes)[b * MGT + t];
        float mx = fmaxf(fmaxf(g.x, g.y), fmaxf(g.z, g.w));
        bool valid = (mx >= 0.0f);
        sg[t] = g;
        sga[t] = (g.z - g.x) * (g.w - g.y);
        nv = __syncthreads_count(valid);         // valid gts are a prefix
    }

    if (s < 8) {
        const int base = s * 1024 + t;
        float4 B[4]; float ab[4], bi[4], bu[4]; int mi[4];
#pragma unroll
        for (int k = 0; k < 4; ++k) {
            B[k]  = ((const float4*)boxes)[b * NBOX + base + k * 256];
            ab[k] = (B[k].z - B[k].x) * (B[k].w - B[k].y);
            bi[k] = 0.0f; bu[k] = 1.0f; mi[k] = 0;
        }
        iou_loop<4>(nv, sg, sga, B, ab, bi, bu, mi);
#pragma unroll
        for (int k = 0; k < 4; ++k) {
            bool pos = (bi[k] > 0.0f) && (__fdiv_rn(bi[k], bu[k]) >= 0.5f);
            emit(b, base + k * 256, pos, mi[k]);
        }
    } else {
        const int i = NBOX + t;   // candidate == gt box t
        float4 B[1]; float ab[1], bi[1], bu[1]; int mi[1];
        B[0]  = ((const float4*)gt_boxes)[b * MGT + t];
        ab[0] = (B[0].z - B[0].x) * (B[0].w - B[0].y);
        bi[0] = 0.0f; bu[0] = 1.0f; mi[0] = 0;
        iou_loop<1>(nv, sg, sga, B, ab, bi, bu, mi);
        bool pos = (bi[0] > 0.0f) && (__fdiv_rn(bi[0], bu[0]) >= 0.5f);
        emit(b, i, pos, mi[0]);
    }
}

// ---------------------------------------------------------------------------
// Kernel 2: per-image select over compacted survivors (~1300) + rank + gather.
// 32 CTAs x 512 threads. Resets g_cnt[b] for the next graph replay.
// ---------------------------------------------------------------------------
__global__ __launch_bounds__(512)
void roi_sample_kernel(const float* __restrict__ boxes,
                       const float* __restrict__ gt_boxes,
                       const int*   __restrict__ gt_classes,
                       float* __restrict__ out) {
    extern __shared__ unsigned long long items[];   // KCAP
    __shared__ unsigned hP[KBIN], hN[KBIN], sPc[KBIN], sNc[KBIN];
    __shared__ unsigned wtP[8], wtN[8];
    __shared__ unsigned long long LP[LCAP], LN[LCAP], selk[NSAMP];
    __shared__ unsigned sh_bp, sh_bn, sh_befP, sh_befN;
    __shared__ unsigned cntP, cntN, cntS;
    __shared__ unsigned long long sh_KP, sh_KN;

    const int b = blockIdx.x;
    const int t = threadIdx.x;
    const int T = 512;
    const int lane = t & 31, wid = t >> 5;

    if (t == 0) { cntP = 0; cntN = 0; cntS = 0; sh_KP = MASK37; sh_KN = MASK37; }
    if (t < KBIN) { hP[t] = 0u; hN[t] = 0u; }
    const unsigned M0 = g_cnt[b];
    const unsigned M = (M0 < KCAP) ? M0 : KCAP;
    __syncthreads();
    if (t == 0) g_cnt[b] = 0u;   // reset for next replay (all threads read M0 above)

    // load survivors + histograms. Positives: inv_m bits [15:23) (w>>29).
    // Negatives have inv_m < 2^20 -> bin on inv_m bits [12:20) (w>>26).
    for (unsigned p = t; p < M; p += T) {
        unsigned long long w = g_sel[b * KCAP + p];
        items[p] = w;
        if ((w >> 37) & 1ull) atomicAdd(&hP[(unsigned)(w >> 29) & 0xFFu], 1u);
        else                  atomicAdd(&hN[(unsigned)(w >> 26) & 0xFFu], 1u);
    }
    __syncthreads();

    // inclusive scan of 256 bins: warp shuffles + tiny cross-warp combine
    unsigned sP = 0, sN = 0;
    if (t < KBIN) {
        sP = hP[t]; sN = hN[t];
#pragma unroll
        for (int off = 1; off < 32; off <<= 1) {
            unsigned vP = __shfl_up_sync(0xFFFFFFFFu, sP, off);
            unsigned vN = __shfl_up_sync(0xFFFFFFFFu, sN, off);
            if (lane >= off) { sP += vP; sN += vN; }
        }
        if (lane == 31) { wtP[wid] = sP; wtN[wid] = sN; }
    }
    __syncthreads();
    if (t < KBIN) {
        unsigned offP = 0, offN = 0;
        for (int ww = 0; ww < wid; ++ww) { offP += wtP[ww]; offN += wtN[ww]; }
        sPc[t] = sP + offP; sNc[t] = sN + offN;
    }
    __syncthreads();

    const unsigned total_pos = sPc[KBIN - 1];
    const unsigned n_pos = (total_pos < (unsigned)NFG) ? total_pos : (unsigned)NFG;
    const unsigned quota = (unsigned)NSAMP - n_pos;
    const bool needPsel = (total_pos > (unsigned)NFG);

    // boundary bins
    if (t < KBIN) {
        unsigned iP = sPc[t], pP = t ? sPc[t - 1] : 0u;
        unsigned iN = sNc[t], pN = t ? sNc[t - 1] : 0u;
        if (needPsel && iP >= (unsigned)NFG && pP < (unsigned)NFG) { sh_bp = (unsigned)t; sh_befP = pP; }
        if (iN >= quota && pN < quota) { sh_bn = (unsigned)t; sh_befN = pN; }
    }
    __syncthreads();

    // collect boundary-bin items (masked 37-bit keys)
    {
        unsigned bp = needPsel ? sh_bp : 0xFFFFFFFFu;
        unsigned bn = sh_bn;
        for (unsigned p = t; p < M; p += T) {
            unsigned long long w = items[p];
            if ((w >> 37) & 1ull) {
                if (((unsigned)(w >> 29) & 0xFFu) == bp) {
                    unsigned j = atomicAdd(&cntP, 1u); if (j < LCAP) LP[j] = w & MASK37;
                }
            } else {
                if (((unsigned)(w >> 26) & 0xFFu) == bn) {
                    unsigned j = atomicAdd(&cntN, 1u); if (j < LCAP) LN[j] = w & MASK37;
                }
            }
        }
    }
    selk[t] = ~0ull;
    __syncthreads();

    // exact rank within boundary bins -> cutoff keys (keys are unique)
    {
        unsigned cp = cntP < LCAP ? cntP : LCAP;
        unsigned cn = cntN < LCAP ? cntN : LCAP;
        if (needPsel && (unsigned)t < cp) {
            unsigned long long k = LP[t]; unsigned r = 0;
            for (unsigned l = 0; l < cp; ++l) r += (LP[l] < k);
            if (r == ((unsigned)NFG - sh_befP) - 1u) sh_KP = k;
        }
        if ((unsigned)t < cn) {
            unsigned long long k = LN[t]; unsigned r = 0;
            for (unsigned l = 0; l < cn; ++l) r += (LN[l] < k);
            if (r == (quota - sh_befN) - 1u) sh_KN = k;
        }
    }
    __syncthreads();

    // final selection (exactly 512); re-key by RNE-rounded score mantissa.
    // score = 2.0f + r rounds r's 23-bit mantissa m to 2^-22 grid:
    //   h = (m>>1) + ((m&1) & ((m>>1)&1)); ties broken by idx asc.
    {
        unsigned long long KP = sh_KP, KN = sh_KN;
        for (unsigned p = t; p < M; p += T) {
            unsigned long long w = items[p];
            unsigned long long kk = w & MASK37;
            bool sel = ((w >> 37) & 1ull) ? (kk <= KP) : (kk <= KN);
            if (sel) {
                unsigned mm = 0x7FFFFFu - (unsigned)((w >> 14) & 0x7FFFFFu);
                unsigned h  = (mm >> 1) + ((mm & 1u) & ((mm >> 1) & 1u));
                unsigned j  = atomicAdd(&cntS, 1u);
                selk[j] = (w & ~MASK37)                        // keep pos|mi high bits
                        | (((unsigned long long)(0x7FFFFFu - h)) << 14)
                        | (w & 0x3FFFull);
            }
        }
    }
    __syncthreads();

    // counting-rank over the 512 selected keys (low 37 bits asc == score desc,
    // idx asc). Keys unique -> ranks are a permutation; no sort needed.
    {
        unsigned long long v = selk[t];
        unsigned long long vs = v << 27;
        unsigned r = 0;
#pragma unroll 8
        for (int l = 0; l < NSAMP; ++l)
            r += ((selk[l] << 27) < vs);       // broadcast smem reads

        if ((unsigned)t < cntS) {
            unsigned i  = (unsigned)(v & 0x3FFFu);
            bool pos    = (v >> 37) & 1ull;
            int  mi     = (int)((v >> 38) & 0xFFull);
            float4 roi = (i < NBOX)
                ? ((const float4*)boxes)[b * NBOX + i]
                : ((const float4*)gt_boxes)[b * MGT + (i - NBOX)];
            float4 gb = make_float4(0.f, 0.f, 0.f, 0.f);
            float cls = 0.0f, gidx = -1.0f;
            if (pos) {
                gb   = ((const float4*)gt_boxes)[b * MGT + mi];
                cls  = (float)gt_classes[b * MGT + mi];
                gidx = (float)mi;
            }
            size_t base = (size_t)(b * NSAMP + r);
            float* o1 = out + base * 4;                                   // rois
            o1[0] = roi.x; o1[1] = roi.y; o1[2] = roi.z; o1[3] = roi.w;
            float* o2 = out + (size_t)BB * NSAMP * 4 + base * 4;          // matched gt boxes
            o2[0] = gb.x; o2[1] = gb.y; o2[2] = gb.z; o2[3] = gb.w;
            out[(size_t)2 * BB * NSAMP * 4 + base] = cls;                 // classes
            out[(size_t)2 * BB * NSAMP * 4 + (size_t)BB * NSAMP + base] = gidx; // indices
        }
    }
}

extern "C" void kernel_launch(void* const* d_in, const int* in_sizes, int n_in,
                              void* d_out, int out_size) {
    (void)out_size;
    const float* boxes      = (const float*)d_in[0];
    const float* gt_boxes   = (const float*)d_in[1];
    const int*   gt_classes = (const int*)d_in[2];
    for (int k = 0; k < n_in; ++k) {
        if (in_sizes[k] == BB * NBOX * 4) boxes      = (const float*)d_in[k];
        else if (in_sizes[k] == BB * MGT * 4) gt_boxes = (const float*)d_in[k];
        else if (in_sizes[k] == BB * MGT)     gt_classes = (const int*)d_in[k];
    }
    float* out = (float*)d_out;

    dim3 g1(BB, 9);    // x = image -> consecutive bids mix images across SMs
    roi_match_kernel<<<g1, 256>>>(boxes, gt_boxes);

    size_t smem = (size_t)KCAP * 8;   // 32 KB dynamic (items)
    cudaFuncSetAttribute(roi_sample_kernel,
                         cudaFuncAttributeMaxDynamicSharedMemorySize, (int)smem);
    roi_sample_kernel<<<BB, 512, smem>>>(boxes, gt_boxes, gt_classes, out);
}

// round 10
// speedup vs baseline: 1.0656x; 1.0656x over previous
#include <cuda_runtime.h>
#include <stdint.h>

#define BB    32
#define NBOX  8192
#define MGT   256
#define NP    8448        // NBOX + MGT
#define NSAMP 512
#define NFG   128
#define KBIN  256
#define KCAP  4096
#define LCAP  256
#define THRESH (1u << 20)            // keep negatives with inv_m < 2^20 (r > 0.875)
#define MASK37 ((1ull << 37) - 1)

// scratch (device globals -- no allocation allowed; zero-initialized at load,
// and kernel 2 re-zeroes g_cnt after consuming it -> graph-replay safe)
__device__ unsigned long long g_sel[BB * KCAP];
__device__ unsigned int       g_cnt[BB];

__device__ __forceinline__ uint32_t rotl32(uint32_t x, int d) {
    return (x << d) | (x >> (32 - d));
}

// JAX *partitionable* threefry, key = (0, 42). bits(p) = x0 ^ x1 of
// threefry2x32((0,42), (0, p))
__device__ __forceinline__ uint32_t threefry_bits(uint32_t p) {
    const uint32_t ks0 = 0u, ks1 = 42u, ks2 = 0x1BD11BF0u;  // 0x1BD11BDA ^ 0 ^ 42
    uint32_t x0 = 0u + ks0;
    uint32_t x1 = p + ks1;
#define TF_R(r) { x0 += x1; x1 = rotl32(x1, (r)); x1 ^= x0; }
    TF_R(13) TF_R(15) TF_R(26) TF_R(6)   x0 += ks1; x1 += ks2 + 1u;
    TF_R(17) TF_R(29) TF_R(16) TF_R(24)  x0 += ks2; x1 += ks0 + 2u;
    TF_R(13) TF_R(15) TF_R(26) TF_R(6)   x0 += ks0; x1 += ks1 + 3u;
    TF_R(17) TF_R(29) TF_R(16) TF_R(24)  x0 += ks1; x1 += ks2 + 4u;
    TF_R(13) TF_R(15) TF_R(26) TF_R(6)   x0 += ks2; x1 += ks0 + 5u;
#undef TF_R
    return x0 ^ x1;
}

// packed survivor word: [0:14) idx | [14:37) inv_m | bit37 pos | [38:46) mi
__device__ __forceinline__ void emit(int b, int i, bool pos, int mi) {
    uint32_t m = threefry_bits((uint32_t)(b * NP + i)) >> 9;
    uint32_t invm = 0x7FFFFFu - m;     // asc == r desc
    if (pos || invm < THRESH) {
        unsigned long long w = ((unsigned long long)(unsigned)mi << 38)
            | ((unsigned long long)(pos ? 1u : 0u) << 37)
            | ((unsigned long long)invm << 14) | (unsigned)i;
        unsigned j = atomicAdd(&g_cnt[b], 1u);
        if (j < KCAP) g_sel[b * KCAP + j] = w;
    }
}

// one guarded IoU-argmax step (the empirically fastest form)
#define IOU_STEP(A, ab, bi, bu, mi)                                     \
    {                                                                   \
        float dy = fminf(A.z, gb.z) - fmaxf(A.x, gb.x);                 \
        float dx = fminf(A.w, gb.w) - fmaxf(A.y, gb.y);                 \
        if (dy > 0.0f && dx > 0.0f) {                                   \
            float inter = dy * dx;                                      \
            float uni   = (ab + ga) - inter;                            \
            if (inter * bu > bi * uni) { bi = inter; bu = uni; mi = g; }\
        }                                                               \
    }

// ---------------------------------------------------------------------------
// Kernel 1: max-IoU matching, 4 boxes/thread in explicit scalars, guarded
// update, valid-gt prefix; emits prefiltered survivors (compacted).
// grid (32, 9): x = image; y slices 0..7 -> 1024 proposals each; 8 -> gts.
// ---------------------------------------------------------------------------
__global__ __launch_bounds__(256)
void roi_match_kernel(const float* __restrict__ boxes,
                      const float* __restrict__ gt_boxes) {
    __shared__ float4 sg[MGT];
    __shared__ float  sga[MGT];

    const int b = blockIdx.x;
    const int s = blockIdx.y;
    const int t = threadIdx.x;
    int nv;
    {
        float4 g = ((const float4*)gt_boxes)[b * MGT + t];
        float mx = fmaxf(fmaxf(g.x, g.y), fmaxf(g.z, g.w));
        bool valid = (mx >= 0.0f);
        sg[t] = g;
        sga[t] = (g.z - g.x) * (g.w - g.y);
        nv = __syncthreads_count(valid);         // valid gts are a prefix
    }

    if (s < 8) {
        const int base = s * 1024 + t;
        float4 A0 = ((const float4*)boxes)[b * NBOX + base];
        float4 A1 = ((const float4*)boxes)[b * NBOX + base + 256];
        float4 A2 = ((const float4*)boxes)[b * NBOX + base + 512];
        float4 A3 = ((const float4*)boxes)[b * NBOX + base + 768];
        const float ab0 = (A0.z - A0.x) * (A0.w - A0.y);
        const float ab1 = (A1.z - A1.x) * (A1.w - A1.y);
        const float ab2 = (A2.z - A2.x) * (A2.w - A2.y);
        const float ab3 = (A3.z - A3.x) * (A3.w - A3.y);
        // bi=-1 sentinel: first overlapping gt always wins; bi>0 <=> overlap
        float bi0 = -1.0f, bu0 = 1.0f; int mi0 = 0;
        float bi1 = -1.0f, bu1 = 1.0f; int mi1 = 0;
        float bi2 = -1.0f, bu2 = 1.0f; int mi2 = 0;
        float bi3 = -1.0f, bu3 = 1.0f; int mi3 = 0;
#pragma unroll 2
        for (int g = 0; g < nv; ++g) {
            float4 gb = sg[g];
            float  ga = sga[g];
            IOU_STEP(A0, ab0, bi0, bu0, mi0)
            IOU_STEP(A1, ab1, bi1, bu1, mi1)
            IOU_STEP(A2, ab2, bi2, bu2, mi2)
            IOU_STEP(A3, ab3, bi3, bu3, mi3)
        }
        bool p0 = (bi0 > 0.0f) && (__fdiv_rn(bi0, bu0) >= 0.5f);
        bool p1 = (bi1 > 0.0f) && (__fdiv_rn(bi1, bu1) >= 0.5f);
        bool p2 = (bi2 > 0.0f) && (__fdiv_rn(bi2, bu2) >= 0.5f);
        bool p3 = (bi3 > 0.0f) && (__fdiv_rn(bi3, bu3) >= 0.5f);
        emit(b, base,       p0, mi0);
        emit(b, base + 256, p1, mi1);
        emit(b, base + 512, p2, mi2);
        emit(b, base + 768, p3, mi3);
    } else {
        const int i = NBOX + t;   // candidate == gt box t
        float4 A0 = ((const float4*)gt_boxes)[b * MGT + t];
        const float ab0 = (A0.z - A0.x) * (A0.w - A0.y);
        float bi0 = -1.0f, bu0 = 1.0f; int mi0 = 0;
#pragma unroll 4
        for (int g = 0; g < nv; ++g) {
            float4 gb = sg[g];
            float  ga = sga[g];
            IOU_STEP(A0, ab0, bi0, bu0, mi0)
        }
        bool p0 = (bi0 > 0.0f) && (__fdiv_rn(bi0, bu0) >= 0.5f);
        emit(b, i, p0, mi0);
    }
}

// ---------------------------------------------------------------------------
// Kernel 2: per-image select over compacted survivors (~1300) + 512-sort.
// (round-8 structure, verbatim) 32 CTAs x 512 threads.
// ---------------------------------------------------------------------------
__global__ __launch_bounds__(512)
void roi_sample_kernel(const float* __restrict__ boxes,
                       const float* __restrict__ gt_boxes,
                       const int*   __restrict__ gt_classes,
                       float* __restrict__ out) {
    extern __shared__ unsigned long long items[];   // KCAP
    __shared__ unsigned hP[KBIN], hN[KBIN], sPc[KBIN], sNc[KBIN];
    __shared__ unsigned wtP[8], wtN[8];
    __shared__ unsigned long long LP[LCAP], LN[LCAP], selk[NSAMP];
    __shared__ unsigned sh_bp, sh_bn, sh_befP, sh_befN;
    __shared__ unsigned cntP, cntN, cntS;
    __shared__ unsigned long long sh_KP, sh_KN;

    const int b = blockIdx.x;
    const int t = threadIdx.x;
    const int T = 512;
    const int lane = t & 31, wid = t >> 5;

    if (t == 0) { cntP = 0; cntN = 0; cntS = 0; sh_KP = MASK37; sh_KN = MASK37; }
    if (t < KBIN) { hP[t] = 0u; hN[t] = 0u; }
    const unsigned M0 = g_cnt[b];
    const unsigned M = (M0 < KCAP) ? M0 : KCAP;
    __syncthreads();
    if (t == 0) g_cnt[b] = 0u;   // reset for next replay (all threads read M0 above)

    // load survivors + histogram on inv_m[22:15]  (bits 29..36 of w)
    for (unsigned p = t; p < M; p += T) {
        unsigned long long w = g_sel[b * KCAP + p];
        items[p] = w;
        unsigned bin = (unsigned)(w >> 29) & 0xFFu;
        if ((w >> 37) & 1ull) atomicAdd(&hP[bin], 1u);
        else                  atomicAdd(&hN[bin], 1u);
    }
    __syncthreads();

    // inclusive scan of 256 bins: warp shuffles + tiny cross-warp combine
    unsigned sP = 0, sN = 0;
    if (t < KBIN) {
        sP = hP[t]; sN = hN[t];
#pragma unroll
        for (int off = 1; off < 32; off <<= 1) {
            unsigned vP = __shfl_up_sync(0xFFFFFFFFu, sP, off);
            unsigned vN = __shfl_up_sync(0xFFFFFFFFu, sN, off);
            if (lane >= off) { sP += vP; sN += vN; }
        }
        if (lane == 31) { wtP[wid] = sP; wtN[wid] = sN; }
    }
    __syncthreads();
    if (t < KBIN) {
        unsigned offP = 0, offN = 0;
        for (int ww = 0; ww < wid; ++ww) { offP += wtP[ww]; offN += wtN[ww]; }
        sPc[t] = sP + offP; sNc[t] = sN + offN;
    }
    __syncthreads();

    const unsigned total_pos = sPc[KBIN - 1];
    const unsigned n_pos = (total_pos < (unsigned)NFG) ? total_pos : (unsigned)NFG;
    const unsigned quota = (unsigned)NSAMP - n_pos;
    const bool needPsel = (total_pos > (unsigned)NFG);

    // boundary bins
    if (t < KBIN) {
        unsigned iP = sPc[t], pP = t ? sPc[t - 1] : 0u;
        unsigned iN = sNc[t], pN = t ? sNc[t - 1] : 0u;
        if (needPsel && iP >= (unsigned)NFG && pP < (unsigned)NFG) { sh_bp = (unsigned)t; sh_befP = pP; }
        if (iN >= quota && pN < quota) { sh_bn = (unsigned)t; sh_befN = pN; }
    }
    __syncthreads();

    // collect boundary-bin items (masked 37-bit keys)
    {
        unsigned bp = needPsel ? sh_bp : 0xFFFFFFFFu;
        unsigned bn = sh_bn;
        for (unsigned p = t; p < M; p += T) {
            unsigned long long w = items[p];
            unsigned bin = (unsigned)(w >> 29) & 0xFFu;
            if ((w >> 37) & 1ull) {
                if (bin == bp) { unsigned j = atomicAdd(&cntP, 1u); if (j < LCAP) LP[j] = w & MASK37; }
            } else {
                if (bin == bn) { unsigned j = atomicAdd(&cntN, 1u); if (j < LCAP) LN[j] = w & MASK37; }
            }
        }
    }
    selk[t] = ~0ull;
    __syncthreads();

    // exact rank within boundary bins -> cutoff keys (keys are unique)
    {
        unsigned cp = cntP < LCAP ? cntP : LCAP;
        unsigned cn = cntN < LCAP ? cntN : LCAP;
        if (needPsel && (unsigned)t < cp) {
            unsigned long long k = LP[t]; unsigned r = 0;
            for (unsigned l = 0; l < cp; ++l) r += (LP[l] < k);
            if (r == ((unsigned)NFG - sh_befP) - 1u) sh_KP = k;
        }
        if ((unsigned)t < cn) {
            unsigned long long k = LN[t]; unsigned r = 0;
            for (unsigned l = 0; l < cn; ++l) r += (LN[l] < k);
            if (r == (quota - sh_befN) - 1u) sh_KN = k;
        }
    }
    __syncthreads();

    // final selection (exactly 512); re-key by RNE-rounded score mantissa.
    // score = 2.0f + r rounds r's 23-bit mantissa m to 2^-22 grid:
    //   h = (m>>1) + ((m&1) & ((m>>1)&1)); ties broken by idx asc.
    {
        unsigned long long KP = sh_KP, KN = sh_KN;
        for (unsigned p = t; p < M; p += T) {
            unsigned long long w = items[p];
            unsigned long long kk = w & MASK37;
            bool sel = ((w >> 37) & 1ull) ? (kk <= KP) : (kk <= KN);
            if (sel) {
                unsigned mm = 0x7FFFFFu - (unsigned)((w >> 14) & 0x7FFFFFu);
                unsigned h  = (mm >> 1) + ((mm & 1u) & ((mm >> 1) & 1u));
                unsigned j  = atomicAdd(&cntS, 1u);
                selk[j] = (w & ~MASK37)                        // keep pos|mi high bits
                        | (((unsigned long long)(0x7FFFFFu - h)) << 14)
                        | (w & 0x3FFFull);
            }
        }
    }
    __syncthreads();

    // bitonic sort 512 keys by low 37 bits asc (== score desc, idx asc);
    // pos/mi ride in the high bits, masked out of comparisons via <<27.
    for (unsigned k = 2; k <= (unsigned)NSAMP; k <<= 1) {
        for (unsigned j = k >> 1; j > 0; j >>= 1) {
            unsigned p = (unsigned)t, q = p ^ j;
            if (q > p) {
                unsigned long long a = selk[p], c = selk[q];
                bool up = ((p & k) == 0);
                if (((a << 27) > (c << 27)) == up) { selk[p] = c; selk[q] = a; }
            }
            __syncthreads();
        }
    }

    // gather outputs
    {
        unsigned long long v = selk[t];
        if ((unsigned)t < cntS) {
            unsigned i  = (unsigned)(v & 0x3FFFu);
            bool pos    = (v >> 37) & 1ull;
            int  mi     = (int)((v >> 38) & 0xFFull);
            float4 roi = (i < NBOX)
                ? ((const float4*)boxes)[b * NBOX + i]
                : ((const float4*)gt_boxes)[b * MGT + (i - NBOX)];
            float4 gb = make_float4(0.f, 0.f, 0.f, 0.f);
            float cls = 0.0f, gidx = -1.0f;
            if (pos) {
                gb   = ((const float4*)gt_boxes)[b * MGT + mi];
                cls  = (float)gt_classes[b * MGT + mi];
                gidx = (float)mi;
            }
            size_t base = (size_t)(b * NSAMP + t);
            float* o1 = out + base * 4;                                   // rois
            o1[0] = roi.x; o1[1] = roi.y; o1[2] = roi.z; o1[3] = roi.w;
            float* o2 = out + (size_t)BB * NSAMP * 4 + base * 4;          // matched gt boxes
            o2[0] = gb.x; o2[1] = gb.y; o2[2] = gb.z; o2[3] = gb.w;
            out[(size_t)2 * BB * NSAMP * 4 + base] = cls;                 // classes
            out[(size_t)2 * BB * NSAMP * 4 + (size_t)BB * NSAMP + base] = gidx; // indices
        }
    }
}

extern "C" void kernel_launch(void* const* d_in, const int* in_sizes, int n_in,
                              void* d_out, int out_size) {
    (void)out_size;
    const float* boxes      = (const float*)d_in[0];
    const float* gt_boxes   = (const float*)d_in[1];
    const int*   gt_classes = (const int*)d_in[2];
    for (int k = 0; k < n_in; ++k) {
        if (in_sizes[k] == BB * NBOX * 4) boxes      = (const float*)d_in[k];
        else if (in_sizes[k] == BB * MGT * 4) gt_boxes = (const float*)d_in[k];
        else if (in_sizes[k] == BB * MGT)     gt_classes = (const int*)d_in[k];
    }
    float* out = (float*)d_out;

    dim3 g1(BB, 9);    // x = image -> consecutive bids mix images across SMs
    roi_match_kernel<<<g1, 256>>>(boxes, gt_boxes);

    size_t smem = (size_t)KCAP * 8;   // 32 KB dynamic (items)
    cudaFuncSetAttribute(roi_sample_kernel,
                         cudaFuncAttributeMaxDynamicSharedMemorySize, (int)smem);
    roi_sample_kernel<<<BB, 512, smem>>>(boxes, gt_boxes, gt_classes, out);
}

// round 11
// speedup vs baseline: 1.1782x; 1.1057x over previous
#include <cuda_runtime.h>
#include <stdint.h>

#define BB    32
#define NBOX  8192
#define MGT   256
#define NP    8448        // NBOX + MGT
#define NSAMP 512
#define NFG   128
#define KBIN  256
#define KCAP  4096
#define LCAP  256
#define THRESH (1u << 20)            // keep negatives with inv_m < 2^20 (r > 0.875)
#define MASK37 ((1ull << 37) - 1)

// scratch (device globals -- no allocation allowed; zero-initialized at load,
// and kernel 2 re-zeroes g_cnt after consuming it -> graph-replay safe)
__device__ unsigned long long g_sel[BB * KCAP];
__device__ unsigned int       g_cnt[BB];

__device__ __forceinline__ uint32_t rotl32(uint32_t x, int d) {
    return (x << d) | (x >> (32 - d));
}

// JAX *partitionable* threefry, key = (0, 42). bits(p) = x0 ^ x1 of
// threefry2x32((0,42), (0, p))
__device__ __forceinline__ uint32_t threefry_bits(uint32_t p) {
    const uint32_t ks0 = 0u, ks1 = 42u, ks2 = 0x1BD11BF0u;  // 0x1BD11BDA ^ 0 ^ 42
    uint32_t x0 = 0u + ks0;
    uint32_t x1 = p + ks1;
#define TF_R(r) { x0 += x1; x1 = rotl32(x1, (r)); x1 ^= x0; }
    TF_R(13) TF_R(15) TF_R(26) TF_R(6)   x0 += ks1; x1 += ks2 + 1u;
    TF_R(17) TF_R(29) TF_R(16) TF_R(24)  x0 += ks2; x1 += ks0 + 2u;
    TF_R(13) TF_R(15) TF_R(26) TF_R(6)   x0 += ks0; x1 += ks1 + 3u;
    TF_R(17) TF_R(29) TF_R(16) TF_R(24)  x0 += ks1; x1 += ks2 + 4u;
    TF_R(13) TF_R(15) TF_R(26) TF_R(6)   x0 += ks2; x1 += ks0 + 5u;
#undef TF_R
    return x0 ^ x1;
}

// packed survivor word: [0:14) idx | [14:37) inv_m | bit37 pos | [38:46) mi
__device__ __forceinline__ void emit(int b, int i, bool pos, int mi) {
    uint32_t m = threefry_bits((uint32_t)(b * NP + i)) >> 9;
    uint32_t invm = 0x7FFFFFu - m;     // asc == r desc
    if (pos || invm < THRESH) {
        unsigned long long w = ((unsigned long long)(unsigned)mi << 38)
            | ((unsigned long long)(pos ? 1u : 0u) << 37)
            | ((unsigned long long)invm << 14) | (unsigned)i;
        unsigned j = atomicAdd(&g_cnt[b], 1u);
        if (j < KCAP) g_sel[b * KCAP + j] = w;
    }
}

// ---------------------------------------------------------------------------
// Kernel 1: max-IoU matching, 2 boxes/thread, ONE branch region per gt
// (merged overlap test), guarded updates inside (bit-identical semantics).
// grid (32, 17): x = image; y slices 0..15 -> 512 proposals each; 16 -> gts.
// ---------------------------------------------------------------------------
__global__ __launch_bounds__(256)
void roi_match_kernel(const float* __restrict__ boxes,
                      const float* __restrict__ gt_boxes) {
    __shared__ float4 sg[MGT];
    __shared__ float  sga[MGT];

    const int b = blockIdx.x;
    const int s = blockIdx.y;
    const int t = threadIdx.x;
    int nv;
    {
        float4 g = ((const float4*)gt_boxes)[b * MGT + t];
        float mx = fmaxf(fmaxf(g.x, g.y), fmaxf(g.z, g.w));
        bool valid = (mx >= 0.0f);
        sg[t] = g;
        sga[t] = (g.z - g.x) * (g.w - g.y);
        nv = __syncthreads_count(valid);         // valid gts are a prefix
    }

    const bool two = (s < 16);
    const int i0 = two ? (s * 512 + t) : (NBOX + t);
    const int i1 = i0 + 256;

    float4 A = (i0 < NBOX) ? ((const float4*)boxes)[b * NBOX + i0]
                           : ((const float4*)gt_boxes)[b * MGT + (i0 - NBOX)];
    float4 Bx = two ? ((const float4*)boxes)[b * NBOX + i1] : A;

    const float abA = (A.z - A.x) * (A.w - A.y);
    const float abB = (Bx.z - Bx.x) * (Bx.w - Bx.y);

    // running argmax of iou = inter/uni via cross-multiplication.
    // bi=-1 sentinel: first overlapping gt always wins; bi>0 <=> overlap.
    float biA = -1.0f, buA = 1.0f; int miA = 0;
    float biB = -1.0f, buB = 1.0f; int miB = 0;
#pragma unroll 4
    for (int g = 0; g < nv; ++g) {
        float4 gb = sg[g];
        float ga  = sga[g];
        float dyA = fminf(A.z,  gb.z) - fmaxf(A.x,  gb.x);
        float dxA = fminf(A.w,  gb.w) - fmaxf(A.y,  gb.y);
        float dyB = fminf(Bx.z, gb.z) - fmaxf(Bx.x, gb.x);
        float dxB = fminf(Bx.w, gb.w) - fmaxf(Bx.y, gb.y);
        float mA  = fminf(dyA, dxA);
        float mB  = fminf(dyB, dxB);
        // single branch region: taken only if at least one box overlaps gt g
        if (fmaxf(mA, mB) > 0.0f) {
            if (mA > 0.0f) {                       // == dyA>0 && dxA>0
                float inter = dyA * dxA;
                float uni   = (abA + ga) - inter;
                if (inter * buA > biA * uni) { biA = inter; buA = uni; miA = g; }
            }
            if (mB > 0.0f) {                       // == dyB>0 && dxB>0
                float inter = dyB * dxB;
                float uni   = (abB + ga) - inter;
                if (inter * buB > biB * uni) { biB = inter; buB = uni; miB = g; }
            }
        }
    }
    bool posA = (biA > 0.0f) && (__fdiv_rn(biA, buA) >= 0.5f);
    bool posB = (biB > 0.0f) && (__fdiv_rn(biB, buB) >= 0.5f);

    emit(b, i0, posA, miA);
    if (two) emit(b, i1, posB, miB);
}

// ---------------------------------------------------------------------------
// Kernel 2: per-image select over compacted survivors (~1300) + 512-sort.
// (round-8 structure, verbatim) 32 CTAs x 512 threads.
// ---------------------------------------------------------------------------
__global__ __launch_bounds__(512)
void roi_sample_kernel(const float* __restrict__ boxes,
                       const float* __restrict__ gt_boxes,
                       const int*   __restrict__ gt_classes,
                       float* __restrict__ out) {
    extern __shared__ unsigned long long items[];   // KCAP
    __shared__ unsigned hP[KBIN], hN[KBIN], sPc[KBIN], sNc[KBIN];
    __shared__ unsigned wtP[8], wtN[8];
    __shared__ unsigned long long LP[LCAP], LN[LCAP], selk[NSAMP];
    __shared__ unsigned sh_bp, sh_bn, sh_befP, sh_befN;
    __shared__ unsigned cntP, cntN, cntS;
    __shared__ unsigned long long sh_KP, sh_KN;

    const int b = blockIdx.x;
    const int t = threadIdx.x;
    const int T = 512;
    const int lane = t & 31, wid = t >> 5;

    if (t == 0) { cntP = 0; cntN = 0; cntS = 0; sh_KP = MASK37; sh_KN = MASK37; }
    if (t < KBIN) { hP[t] = 0u; hN[t] = 0u; }
    const unsigned M0 = g_cnt[b];
    const unsigned M = (M0 < KCAP) ? M0 : KCAP;
    __syncthreads();
    if (t == 0) g_cnt[b] = 0u;   // reset for next replay (all threads read M0 above)

    // load survivors + histogram on inv_m[22:15]  (bits 29..36 of w)
    for (unsigned p = t; p < M; p += T) {
        unsigned long long w = g_sel[b * KCAP + p];
        items[p] = w;
        unsigned bin = (unsigned)(w >> 29) & 0xFFu;
        if ((w >> 37) & 1ull) atomicAdd(&hP[bin], 1u);
        else                  atomicAdd(&hN[bin], 1u);
    }
    __syncthreads();

    // inclusive scan of 256 bins: warp shuffles + tiny cross-warp combine
    unsigned sP = 0, sN = 0;
    if (t < KBIN) {
        sP = hP[t]; sN = hN[t];
#pragma unroll
        for (int off = 1; off < 32; off <<= 1) {
            unsigned vP = __shfl_up_sync(0xFFFFFFFFu, sP, off);
            unsigned vN = __shfl_up_sync(0xFFFFFFFFu, sN, off);
            if (lane >= off) { sP += vP; sN += vN; }
        }
        if (lane == 31) { wtP[wid] = sP; wtN[wid] = sN; }
    }
    __syncthreads();
    if (t < KBIN) {
        unsigned offP = 0, offN = 0;
        for (int ww = 0; ww < wid; ++ww) { offP += wtP[ww]; offN += wtN[ww]; }
        sPc[t] = sP + offP; sNc[t] = sN + offN;
    }
    __syncthreads();

    const unsigned total_pos = sPc[KBIN - 1];
    const unsigned n_pos = (total_pos < (unsigned)NFG) ? total_pos : (unsigned)NFG;
    const unsigned quota = (unsigned)NSAMP - n_pos;
    const bool needPsel = (total_pos > (unsigned)NFG);

    // boundary bins
    if (t < KBIN) {
        unsigned iP = sPc[t], pP = t ? sPc[t - 1] : 0u;
        unsigned iN = sNc[t], pN = t ? sNc[t - 1] : 0u;
        if (needPsel && iP >= (unsigned)NFG && pP < (unsigned)NFG) { sh_bp = (unsigned)t; sh_befP = pP; }
        if (iN >= quota && pN < quota) { sh_bn = (unsigned)t; sh_befN = pN; }
    }
    __syncthreads();

    // collect boundary-bin items (masked 37-bit keys)
    {
        unsigned bp = needPsel ? sh_bp : 0xFFFFFFFFu;
        unsigned bn = sh_bn;
        for (unsigned p = t; p < M; p += T) {
            unsigned long long w = items[p];
            unsigned bin = (unsigned)(w >> 29) & 0xFFu;
            if ((w >> 37) & 1ull) {
                if (bin == bp) { unsigned j = atomicAdd(&cntP, 1u); if (j < LCAP) LP[j] = w & MASK37; }
            } else {
                if (bin == bn) { unsigned j = atomicAdd(&cntN, 1u); if (j < LCAP) LN[j] = w & MASK37; }
            }
        }
    }
    selk[t] = ~0ull;
    __syncthreads();

    // exact rank within boundary bins -> cutoff keys (keys are unique)
    {
        unsigned cp = cntP < LCAP ? cntP : LCAP;
        unsigned cn = cntN < LCAP ? cntN : LCAP;
        if (needPsel && (unsigned)t < cp) {
            unsigned long long k = LP[t]; unsigned r = 0;
            for (unsigned l = 0; l < cp; ++l) r += (LP[l] < k);
            if (r == ((unsigned)NFG - sh_befP) - 1u) sh_KP = k;
        }
        if ((unsigned)t < cn) {
            unsigned long long k = LN[t]; unsigned r = 0;
            for (unsigned l = 0; l < cn; ++l) r += (LN[l] < k);
            if (r == (quota - sh_befN) - 1u) sh_KN = k;
        }
    }
    __syncthreads();

    // final selection (exactly 512); re-key by RNE-rounded score mantissa.
    // score = 2.0f + r rounds r's 23-bit mantissa m to 2^-22 grid:
    //   h = (m>>1) + ((m&1) & ((m>>1)&1)); ties broken by idx asc.
    {
        unsigned long long KP = sh_KP, KN = sh_KN;
        for (unsigned p = t; p < M; p += T) {
            unsigned long long w = items[p];
            unsigned long long kk = w & MASK37;
            bool sel = ((w >> 37) & 1ull) ? (kk <= KP) : (kk <= KN);
            if (sel) {
                unsigned mm = 0x7FFFFFu - (unsigned)((w >> 14) & 0x7FFFFFu);
                unsigned h  = (mm >> 1) + ((mm & 1u) & ((mm >> 1) & 1u));
                unsigned j  = atomicAdd(&cntS, 1u);
                selk[j] = (w & ~MASK37)                        // keep pos|mi high bits
                        | (((unsigned long long)(0x7FFFFFu - h)) << 14)
                        | (w & 0x3FFFull);
            }
        }
    }
    __syncthreads();

    // bitonic sort 512 keys by low 37 bits asc (== score desc, idx asc);
    // pos/mi ride in the high bits, masked out of comparisons via <<27.
    for (unsigned k = 2; k <= (unsigned)NSAMP; k <<= 1) {
        for (unsigned j = k >> 1; j > 0; j >>= 1) {
            unsigned p = (unsigned)t, q = p ^ j;
            if (q > p) {
                unsigned long long a = selk[p], c = selk[q];
                bool up = ((p & k) == 0);
                if (((a << 27) > (c << 27)) == up) { selk[p] = c; selk[q] = a; }
            }
            __syncthreads();
        }
    }

    // gather outputs
    {
        unsigned long long v = selk[t];
        if ((unsigned)t < cntS) {
            unsigned i  = (unsigned)(v & 0x3FFFu);
            bool pos    = (v >> 37) & 1ull;
            int  mi     = (int)((v >> 38) & 0xFFull);
            float4 roi = (i < NBOX)
                ? ((const float4*)boxes)[b * NBOX + i]
                : ((const float4*)gt_boxes)[b * MGT + (i - NBOX)];
            float4 gb = make_float4(0.f, 0.f, 0.f, 0.f);
            float cls = 0.0f, gidx = -1.0f;
            if (pos) {
                gb   = ((const float4*)gt_boxes)[b * MGT + mi];
                cls  = (float)gt_classes[b * MGT + mi];
                gidx = (float)mi;
            }
            size_t base = (size_t)(b * NSAMP + t);
            float* o1 = out + base * 4;                                   // rois
            o1[0] = roi.x; o1[1] = roi.y; o1[2] = roi.z; o1[3] = roi.w;
            float* o2 = out + (size_t)BB * NSAMP * 4 + base * 4;          // matched gt boxes
            o2[0] = gb.x; o2[1] = gb.y; o2[2] = gb.z; o2[3] = gb.w;
            out[(size_t)2 * BB * NSAMP * 4 + base] = cls;                 // classes
            out[(size_t)2 * BB * NSAMP * 4 + (size_t)BB * NSAMP + base] = gidx; // indices
        }
    }
}

extern "C" void kernel_launch(void* const* d_in, const int* in_sizes, int n_in,
                              void* d_out, int out_size) {
    (void)out_size;
    const float* boxes      = (const float*)d_in[0];
    const float* gt_boxes   = (const float*)d_in[1];
    const int*   gt_classes = (const int*)d_in[2];
    for (int k = 0; k < n_in; ++k) {
        if (in_sizes[k] == BB * NBOX * 4) boxes      = (const float*)d_in[k];
        else if (in_sizes[k] == BB * MGT * 4) gt_boxes = (const float*)d_in[k];
        else if (in_sizes[k] == BB * MGT)     gt_classes = (const int*)d_in[k];
    }
    float* out = (float*)d_out;

    dim3 g1(BB, 17);   // x = image -> consecutive bids mix images across SMs
    roi_match_kernel<<<g1, 256>>>(boxes, gt_boxes);

    size_t smem = (size_t)KCAP * 8;   // 32 KB dynamic (items)
    cudaFuncSetAttribute(roi_sample_kernel,
                         cudaFuncAttributeMaxDynamicSharedMemorySize, (int)smem);
    roi_sample_kernel<<<BB, 512, smem>>>(boxes, gt_boxes, gt_classes, out);
}

// round 12
// speedup vs baseline: 1.2280x; 1.0423x over previous
#include <cuda_runtime.h>
#include <stdint.h>

#define BB    32
#define NBOX  8192
#define MGT   256
#define NP    8448        // NBOX + MGT
#define NSAMP 512
#define NFG   128
#define KBIN  256
#define KCAP  4096
#define LCAP  256
#define THRESH (1u << 20)            // keep negatives with inv_m < 2^20 (r > 0.875)
#define MASK37 ((1ull << 37) - 1)

// scratch (device globals -- no allocation allowed; zero-initialized at load;
// consumer CTA resets g_cnt/g_done each run -> graph-replay safe)
__device__ unsigned long long g_sel[BB * KCAP];
__device__ unsigned int       g_cnt[BB];
__device__ unsigned int       g_done[BB];

__device__ __forceinline__ uint32_t rotl32(uint32_t x, int d) {
    return (x << d) | (x >> (32 - d));
}

// JAX *partitionable* threefry, key = (0, 42). bits(p) = x0 ^ x1 of
// threefry2x32((0,42), (0, p))
__device__ __forceinline__ uint32_t threefry_bits(uint32_t p) {
    const uint32_t ks0 = 0u, ks1 = 42u, ks2 = 0x1BD11BF0u;  // 0x1BD11BDA ^ 0 ^ 42
    uint32_t x0 = 0u + ks0;
    uint32_t x1 = p + ks1;
#define TF_R(r) { x0 += x1; x1 = rotl32(x1, (r)); x1 ^= x0; }
    TF_R(13) TF_R(15) TF_R(26) TF_R(6)   x0 += ks1; x1 += ks2 + 1u;
    TF_R(17) TF_R(29) TF_R(16) TF_R(24)  x0 += ks2; x1 += ks0 + 2u;
    TF_R(13) TF_R(15) TF_R(26) TF_R(6)   x0 += ks0; x1 += ks1 + 3u;
    TF_R(17) TF_R(29) TF_R(16) TF_R(24)  x0 += ks1; x1 += ks2 + 4u;
    TF_R(13) TF_R(15) TF_R(26) TF_R(6)   x0 += ks2; x1 += ks0 + 5u;
#undef TF_R
    return x0 ^ x1;
}

// packed survivor word: [0:14) idx | [14:37) inv_m | bit37 pos | [38:46) mi
__device__ __forceinline__ void emit(int b, int i, bool pos, int mi) {
    uint32_t m = threefry_bits((uint32_t)(b * NP + i)) >> 9;
    uint32_t invm = 0x7FFFFFu - m;     // asc == r desc
    if (pos || invm < THRESH) {
        unsigned long long w = ((unsigned long long)(unsigned)mi << 38)
            | ((unsigned long long)(pos ? 1u : 0u) << 37)
            | ((unsigned long long)invm << 14) | (unsigned)i;
        unsigned j = atomicAdd(&g_cnt[b], 1u);
        if (j < KCAP) g_sel[b * KCAP + j] = w;
    }
}

// ---------------------------------------------------------------------------
// Fused kernel. grid (32, 9) x 512 threads.
//   slices 0..7 : round-8 2-box guarded IoU matching over 1024 proposals,
//                 emit survivors, signal g_done[b].
//   slice 8     : match the 256 gt-candidates, then wait for the 8 producer
//                 CTAs of this image and run selection+sort+gather.
// __launch_bounds__(512, 2): >=2 CTAs/SM -> >=296 resident >= 288 launched,
// so the spin-wait cannot deadlock.
// ---------------------------------------------------------------------------
__global__ __launch_bounds__(512, 2)
void roi_fused_kernel(const float* __restrict__ boxes,
                      const float* __restrict__ gt_boxes,
                      const int*   __restrict__ gt_classes,
                      float* __restrict__ out) {
    __shared__ float4 sg[MGT];
    __shared__ float  sga[MGT];
    __shared__ unsigned hP[KBIN], hN[KBIN], sPc[KBIN], sNc[KBIN];
    __shared__ unsigned wtP[8], wtN[8];
    __shared__ unsigned long long LP[LCAP], LN[LCAP], selk[NSAMP];
    __shared__ unsigned sh_bp, sh_bn, sh_befP, sh_befN;
    __shared__ unsigned cntP, cntN, cntS, sh_M;
    __shared__ unsigned long long sh_KP, sh_KN;

    const int b = blockIdx.x;
    const int s = blockIdx.y;
    const int t = threadIdx.x;
    const int T = 512;
    const int lane = t & 31, wid = t >> 5;

    // gt tile (threads 0..255)
    bool valid = false;
    if (t < MGT) {
        float4 g = ((const float4*)gt_boxes)[b * MGT + t];
        float mx = fmaxf(fmaxf(g.x, g.y), fmaxf(g.z, g.w));
        valid = (mx >= 0.0f);
        sg[t] = g;
        sga[t] = (g.z - g.x) * (g.w - g.y);
    }
    const int nv = __syncthreads_count(valid);   // valid gts are a prefix

    if (s < 8) {
        // ---- producer slice: round-8 2-box guarded matching, verbatim ----
        const int i0 = s * 1024 + t;
        const int i1 = i0 + 512;
        float4 A  = ((const float4*)boxes)[b * NBOX + i0];
        float4 Bx = ((const float4*)boxes)[b * NBOX + i1];
        const float abA = (A.z - A.x) * (A.w - A.y);
        const float abB = (Bx.z - Bx.x) * (Bx.w - Bx.y);
        // bi=-1 sentinel: first overlapping gt always wins; bi>0 <=> overlap
        float biA = -1.0f, buA = 1.0f; int miA = 0;
        float biB = -1.0f, buB = 1.0f; int miB = 0;
#pragma unroll 4
        for (int g = 0; g < nv; ++g) {
            float4 gb = sg[g];
            float ga  = sga[g];
            {
                float dy = fminf(A.z, gb.z) - fmaxf(A.x, gb.x);
                float dx = fminf(A.w, gb.w) - fmaxf(A.y, gb.y);
                if (dy > 0.0f && dx > 0.0f) {
                    float inter = dy * dx;
                    float uni   = (abA + ga) - inter;
                    if (inter * buA > biA * uni) { biA = inter; buA = uni; miA = g; }
                }
            }
            {
                float dy = fminf(Bx.z, gb.z) - fmaxf(Bx.x, gb.x);
                float dx = fminf(Bx.w, gb.w) - fmaxf(Bx.y, gb.y);
                if (dy > 0.0f && dx > 0.0f) {
                    float inter = dy * dx;
                    float uni   = (abB + ga) - inter;
                    if (inter * buB > biB * uni) { biB = inter; buB = uni; miB = g; }
                }
            }
        }
        bool posA = (biA > 0.0f) && (__fdiv_rn(biA, buA) >= 0.5f);
        bool posB = (biB > 0.0f) && (__fdiv_rn(biB, buB) >= 0.5f);
        emit(b, i0, posA, miA);
        emit(b, i1, posB, miB);
        __syncthreads();                 // all CTA emits complete
        if (t == 0) {
            __threadfence();             // release g_sel/g_cnt writes
            atomicAdd(&g_done[b], 1u);
        }
        return;
    }

    // ---- slice 8: gt-candidate matching + consumer ----
    if (t == 0) { cntP = 0; cntN = 0; cntS = 0; sh_KP = MASK37; sh_KN = MASK37; }
    if (t < KBIN) { hP[t] = 0u; hN[t] = 0u; }
    if (t < MGT) {
        float4 A = sg[t];                // candidate == gt box t
        const float abA = sga[t];
        float biA = -1.0f, buA = 1.0f; int miA = 0;
#pragma unroll 4
        for (int g = 0; g < nv; ++g) {
            float4 gb = sg[g];
            float ga  = sga[g];
            float dy = fminf(A.z, gb.z) - fmaxf(A.x, gb.x);
            float dx = fminf(A.w, gb.w) - fmaxf(A.y, gb.y);
            if (dy > 0.0f && dx > 0.0f) {
                float inter = dy * dx;
                float uni   = (abA + ga) - inter;
                if (inter * buA > biA * uni) { biA = inter; buA = uni; miA = g; }
            }
        }
        bool posA = (biA > 0.0f) && (__fdiv_rn(biA, buA) >= 0.5f);
        emit(b, NBOX + t, posA, miA);
    }
    __syncthreads();                     // own emits complete

    if (t == 0) {
        __threadfence();
        while (atomicAdd(&g_done[b], 0u) != 8u) __nanosleep(64);
        g_done[b] = 0u;                              // reset for next replay
        sh_M = atomicExch(&g_cnt[b], 0u);            // consume + reset count
    }
    __syncthreads();
    const unsigned M = (sh_M < KCAP) ? sh_M : KCAP;
    const unsigned long long* sel = &g_sel[b * KCAP];

    // histogram on inv_m[22:15] (bits 29..36 of w); stream from L2
    for (unsigned p = t; p < M; p += T) {
        unsigned long long w = __ldcg(&sel[p]);
        unsigned bin = (unsigned)(w >> 29) & 0xFFu;
        if ((w >> 37) & 1ull) atomicAdd(&hP[bin], 1u);
        else                  atomicAdd(&hN[bin], 1u);
    }
    __syncthreads();

    // inclusive scan of 256 bins: warp shuffles + tiny cross-warp combine
    unsigned sP = 0, sN = 0;
    if (t < KBIN) {
        sP = hP[t]; sN = hN[t];
#pragma unroll
        for (int off = 1; off < 32; off <<= 1) {
            unsigned vP = __shfl_up_sync(0xFFFFFFFFu, sP, off);
            unsigned vN = __shfl_up_sync(0xFFFFFFFFu, sN, off);
            if (lane >= off) { sP += vP; sN += vN; }
        }
        if (lane == 31) { wtP[wid] = sP; wtN[wid] = sN; }
    }
    __syncthreads();
    if (t < KBIN) {
        unsigned offP = 0, offN = 0;
        for (int ww = 0; ww < wid; ++ww) { offP += wtP[ww]; offN += wtN[ww]; }
        sPc[t] = sP + offP; sNc[t] = sN + offN;
    }
    __syncthreads();

    const unsigned total_pos = sPc[KBIN - 1];
    const unsigned n_pos = (total_pos < (unsigned)NFG) ? total_pos : (unsigned)NFG;
    const unsigned quota = (unsigned)NSAMP - n_pos;
    const bool needPsel = (total_pos > (unsigned)NFG);

    // boundary bins
    if (t < KBIN) {
        unsigned iP = sPc[t], pP = t ? sPc[t - 1] : 0u;
        unsigned iN = sNc[t], pN = t ? sNc[t - 1] : 0u;
        if (needPsel && iP >= (unsigned)NFG && pP < (unsigned)NFG) { sh_bp = (unsigned)t; sh_befP = pP; }
        if (iN >= quota && pN < quota) { sh_bn = (unsigned)t; sh_befN = pN; }
    }
    __syncthreads();

    // collect boundary-bin items (masked 37-bit keys)
    {
        unsigned bp = needPsel ? sh_bp : 0xFFFFFFFFu;
        unsigned bn = sh_bn;
        for (unsigned p = t; p < M; p += T) {
            unsigned long long w = __ldcg(&sel[p]);
            unsigned bin = (unsigned)(w >> 29) & 0xFFu;
            if ((w >> 37) & 1ull) {
                if (bin == bp) { unsigned j = atomicAdd(&cntP, 1u); if (j < LCAP) LP[j] = w & MASK37; }
            } else {
                if (bin == bn) { unsigned j = atomicAdd(&cntN, 1u); if (j < LCAP) LN[j] = w & MASK37; }
            }
        }
    }
    selk[t] = ~0ull;
    __syncthreads();

    // exact rank within boundary bins -> cutoff keys (keys are unique)
    {
        unsigned cp = cntP < LCAP ? cntP : LCAP;
        unsigned cn = cntN < LCAP ? cntN : LCAP;
        if (needPsel && (unsigned)t < cp) {
            unsigned long long k = LP[t]; unsigned r = 0;
            for (unsigned l = 0; l < cp; ++l) r += (LP[l] < k);
            if (r == ((unsigned)NFG - sh_befP) - 1u) sh_KP = k;
        }
        if ((unsigned)t < cn) {
            unsigned long long k = LN[t]; unsigned r = 0;
            for (unsigned l = 0; l < cn; ++l) r += (LN[l] < k);
            if (r == (quota - sh_befN) - 1u) sh_KN = k;
        }
    }
    __syncthreads();

    // final selection (exactly 512); re-key by RNE-rounded score mantissa.
    // score = 2.0f + r rounds r's 23-bit mantissa m to 2^-22 grid:
    //   h = (m>>1) + ((m&1) & ((m>>1)&1)); ties broken by idx asc.
    {
        unsigned long long KP = sh_KP, KN = sh_KN;
        for (unsigned p = t; p < M; p += T) {
            unsigned long long w = __ldcg(&sel[p]);
            unsigned long long kk = w & MASK37;
            bool selb = ((w >> 37) & 1ull) ? (kk <= KP) : (kk <= KN);
            if (selb) {
                unsigned mm = 0x7FFFFFu - (unsigned)((w >> 14) & 0x7FFFFFu);
                unsigned h  = (mm >> 1) + ((mm & 1u) & ((mm >> 1) & 1u));
                unsigned j  = atomicAdd(&cntS, 1u);
                selk[j] = (w & ~MASK37)                        // keep pos|mi high bits
                        | (((unsigned long long)(0x7FFFFFu - h)) << 14)
                        | (w & 0x3FFFull);
            }
        }
    }
    __syncthreads();

    // bitonic sort 512 keys by low 37 bits asc (== score desc, idx asc);
    // pos/mi ride in the high bits, masked out of comparisons via <<27.
    for (unsigned k = 2; k <= (unsigned)NSAMP; k <<= 1) {
        for (unsigned j = k >> 1; j > 0; j >>= 1) {
            unsigned p = (unsigned)t, q = p ^ j;
            if (q > p) {
                unsigned long long a = selk[p], c = selk[q];
                bool up = ((p & k) == 0);
                if (((a << 27) > (c << 27)) == up) { selk[p] = c; selk[q] = a; }
            }
            __syncthreads();
        }
    }

    // gather outputs
    {
        unsigned long long v = selk[t];
        if ((unsigned)t < cntS) {
            unsigned i  = (unsigned)(v & 0x3FFFu);
            bool pos    = (v >> 37) & 1ull;
            int  mi     = (int)((v >> 38) & 0xFFull);
            float4 roi = (i < NBOX)
                ? ((const float4*)boxes)[b * NBOX + i]
                : ((const float4*)gt_boxes)[b * MGT + (i - NBOX)];
            float4 gb = make_float4(0.f, 0.f, 0.f, 0.f);
            float cls = 0.0f, gidx = -1.0f;
            if (pos) {
                gb   = ((const float4*)gt_boxes)[b * MGT + mi];
                cls  = (float)gt_classes[b * MGT + mi];
                gidx = (float)mi;
            }
            size_t base = (size_t)(b * NSAMP + t);
            float* o1 = out + base * 4;                                   // rois
            o1[0] = roi.x; o1[1] = roi.y; o1[2] = roi.z; o1[3] = roi.w;
            float* o2 = out + (size_t)BB * NSAMP * 4 + base * 4;          // matched gt boxes
            o2[0] = gb.x; o2[1] = gb.y; o2[2] = gb.z; o2[3] = gb.w;
            out[(size_t)2 * BB * NSAMP * 4 + base] = cls;                 // classes
            out[(size_t)2 * BB * NSAMP * 4 + (size_t)BB * NSAMP + base] = gidx; // indices
        }
    }
}

extern "C" void kernel_launch(void* const* d_in, const int* in_sizes, int n_in,
                              void* d_out, int out_size) {
    (void)out_size;
    const float* boxes      = (const float*)d_in[0];
    const float* gt_boxes   = (const float*)d_in[1];
    const int*   gt_classes = (const int*)d_in[2];
    for (int k = 0; k < n_in; ++k) {
        if (in_sizes[k] == BB * NBOX * 4) boxes      = (const float*)d_in[k];
        else if (in_sizes[k] == BB * MGT * 4) gt_boxes = (const float*)d_in[k];
        else if (in_sizes[k] == BB * MGT)     gt_classes = (const int*)d_in[k];
    }
    float* out = (float*)d_out;

    dim3 g(BB, 9);   // 288 CTAs; __launch_bounds__(512,2) -> all resident
    roi_fused_kernel<<<g, 512>>>(boxes, gt_boxes, gt_classes, out);
}

// round 13
// speedup vs baseline: 1.6412x; 1.3365x over previous
#include <cuda_runtime.h>
#include <stdint.h>

#define BB    32
#define NBOX  8192
#define MGT   256
#define NP    8448        // NBOX + MGT
#define NSAMP 512
#define NFG   128
#define KBIN  256
#define KCAP  4096
#define LCAP  256
#define BCAP  2048
#define THRESH (1u << 20)            // keep negatives with inv_m < 2^20 (r > 0.875)
#define MASK37 ((1ull << 37) - 1)

// scratch (device globals -- no allocation allowed; zero-initialized at load;
// k2 resets g_cnt/g_bandcnt each run -> graph-replay safe)
__device__ unsigned long long g_sel[BB * KCAP];
__device__ unsigned int       g_cnt[BB];
__device__ unsigned int       g_bandcnt[BB * 8];
__device__ unsigned short     g_blist[BB * 8 * BCAP];

__device__ __forceinline__ uint32_t rotl32(uint32_t x, int d) {
    return (x << d) | (x >> (32 - d));
}

// JAX *partitionable* threefry, key = (0, 42). bits(p) = x0 ^ x1 of
// threefry2x32((0,42), (0, p))
__device__ __forceinline__ uint32_t threefry_bits(uint32_t p) {
    const uint32_t ks0 = 0u, ks1 = 42u, ks2 = 0x1BD11BF0u;  // 0x1BD11BDA ^ 0 ^ 42
    uint32_t x0 = 0u + ks0;
    uint32_t x1 = p + ks1;
#define TF_R(r) { x0 += x1; x1 = rotl32(x1, (r)); x1 ^= x0; }
    TF_R(13) TF_R(15) TF_R(26) TF_R(6)   x0 += ks1; x1 += ks2 + 1u;
    TF_R(17) TF_R(29) TF_R(16) TF_R(24)  x0 += ks2; x1 += ks0 + 2u;
    TF_R(13) TF_R(15) TF_R(26) TF_R(6)   x0 += ks0; x1 += ks1 + 3u;
    TF_R(17) TF_R(29) TF_R(16) TF_R(24)  x0 += ks1; x1 += ks2 + 4u;
    TF_R(13) TF_R(15) TF_R(26) TF_R(6)   x0 += ks2; x1 += ks0 + 5u;
#undef TF_R
    return x0 ^ x1;
}

// packed survivor word: [0:14) idx | [14:37) inv_m | bit37 pos | [38:46) mi
__device__ __forceinline__ void emit(int b, int i, bool pos, int mi) {
    uint32_t m = threefry_bits((uint32_t)(b * NP + i)) >> 9;
    uint32_t invm = 0x7FFFFFu - m;     // asc == r desc
    if (pos || invm < THRESH) {
        unsigned long long w = ((unsigned long long)(unsigned)mi << 38)
            | ((unsigned long long)(pos ? 1u : 0u) << 37)
            | ((unsigned long long)invm << 14) | (unsigned)i;
        unsigned j = atomicAdd(&g_cnt[b], 1u);
        if (j < KCAP) g_sel[b * KCAP + j] = w;
    }
}

// ---------------------------------------------------------------------------
// Kernel 0: bin boxes by y0 into 8 bands (CTA-aggregated atomics).
// grid (32 slices, 32 images) x 256 threads.
// ---------------------------------------------------------------------------
__global__ __launch_bounds__(256)
void roi_bin_kernel(const float* __restrict__ boxes) {
    __shared__ unsigned scnt[8], sbase[8];
    const int b = blockIdx.y;
    const int i = blockIdx.x * 256 + threadIdx.x;
    if (threadIdx.x < 8) scnt[threadIdx.x] = 0u;
    __syncthreads();
    float y0 = __ldg(&boxes[(size_t)(b * NBOX + i) * 4]);
    int bd = (int)(y0 * 0.0078125f);        // exact: mul by 2^-7
    bd = bd > 7 ? 7 : bd;
    unsigned lofs = atomicAdd(&scnt[bd], 1u);
    __syncthreads();
    if (threadIdx.x < 8)
        sbase[threadIdx.x] = atomicAdd(&g_bandcnt[b * 8 + threadIdx.x], scnt[threadIdx.x]);
    __syncthreads();
    unsigned pos = sbase[bd] + lofs;
    if (pos < BCAP) g_blist[(b * 8 + bd) * BCAP + pos] = (unsigned short)i;
}

// ---------------------------------------------------------------------------
// Kernel 1: max-IoU matching over band-pruned gt candidate lists.
// grid (32, 17): y<16 -> band = y>>1, slice = y&1 over that band's boxes;
// y==16 -> the 256 gt-candidates (full loop). 2 boxes/thread, guarded update
// (frozen round-8 form). Candidate list is an ascending-ordered exact
// superset of overlapping gts -> bit-identical argmax.
// ---------------------------------------------------------------------------
__global__ __launch_bounds__(256)
void roi_match_kernel(const float* __restrict__ boxes,
                      const float* __restrict__ gt_boxes) {
    __shared__ float4 sg[MGT];
    __shared__ float  sga[MGT];
    __shared__ unsigned short gl[MGT];
    __shared__ unsigned wscan[8];
    __shared__ unsigned sh_ngl;

    const int b = blockIdx.x;
    const int y = blockIdx.y;
    const int t = threadIdx.x;
    const int lane = t & 31, wid = t >> 5;

    float4 g4 = ((const float4*)gt_boxes)[b * MGT + t];
    float mx = fmaxf(fmaxf(g4.x, g4.y), fmaxf(g4.z, g4.w));
    bool valid = (mx >= 0.0f);
    sg[t] = g4;
    sga[t] = (g4.z - g4.x) * (g4.w - g4.y);
    const int nv = __syncthreads_count(valid);   // valid gts are a prefix

    if (y == 16) {
        // gt-candidates: full loop (tiny)
        float4 A = sg[t];
        const float abA = sga[t];
        float biA = -1.0f, buA = 1.0f; int miA = 0;
#pragma unroll 4
        for (int g = 0; g < nv; ++g) {
            float4 gb = sg[g];
            float ga  = sga[g];
            float dy = fminf(A.z, gb.z) - fmaxf(A.x, gb.x);
            float dx = fminf(A.w, gb.w) - fmaxf(A.y, gb.y);
            if (dy > 0.0f && dx > 0.0f) {
                float inter = dy * dx;
                float uni   = (abA + ga) - inter;
                if (inter * buA > biA * uni) { biA = inter; buA = uni; miA = g; }
            }
        }
        bool posA = (biA > 0.0f) && (__fdiv_rn(biA, buA) >= 0.5f);
        emit(b, NBOX + t, posA, miA);
        return;
    }

    const int band = y >> 1, slice = y & 1;
    const float blo = (float)(band * 128);
    const float bhi = blo + 264.0f;          // box y-extent within [blo, blo+264)

    // ascending-ordered compaction of candidate gts for this band
    bool memb = (t < nv) && (g4.z > blo) && (g4.x < bhi);
    unsigned mask = __ballot_sync(0xFFFFFFFFu, memb);
    if (lane == 0) wscan[wid] = __popc(mask);
    __syncthreads();
    if (t == 0) {
        unsigned s = 0;
        for (int i2 = 0; i2 < 8; ++i2) { unsigned c = wscan[i2]; wscan[i2] = s; s += c; }
        sh_ngl = s;
    }
    __syncthreads();
    if (memb) gl[wscan[wid] + __popc(mask & ((1u << lane) - 1u))] = (unsigned short)t;
    const int ngl = (int)sh_ngl;
    __syncthreads();

    unsigned cnt = g_bandcnt[b * 8 + band];
    cnt = (cnt < BCAP) ? cnt : BCAP;
    const unsigned half = (cnt + 1u) >> 1;
    const unsigned lob  = slice ? half : 0u;
    const unsigned end  = slice ? cnt : half;
    const unsigned short* list = &g_blist[(b * 8 + band) * BCAP];

    for (unsigned chunk = lob; chunk < end; chunk += 512u) {
        unsigned pA = chunk + (unsigned)t, pB = pA + 256u;
        bool vA = pA < end, vB = pB < end;
        int iA = vA ? (int)list[pA] : 0;
        int iB = vB ? (int)list[pB] : iA;
        float4 A  = ((const float4*)boxes)[b * NBOX + iA];
        float4 Bx = ((const float4*)boxes)[b * NBOX + iB];
        const float abA = (A.z - A.x) * (A.w - A.y);
        const float abB = (Bx.z - Bx.x) * (Bx.w - Bx.y);
        float biA = -1.0f, buA = 1.0f; int miA = 0;
        float biB = -1.0f, buB = 1.0f; int miB = 0;
#pragma unroll 4
        for (int g = 0; g < ngl; ++g) {
            int gid = (int)gl[g];                // uniform broadcast
            float4 gb = sg[gid];
            float ga  = sga[gid];
            {
                float dy = fminf(A.z, gb.z) - fmaxf(A.x, gb.x);
                float dx = fminf(A.w, gb.w) - fmaxf(A.y, gb.y);
                if (dy > 0.0f && dx > 0.0f) {
                    float inter = dy * dx;
                    float uni   = (abA + ga) - inter;
                    if (inter * buA > biA * uni) { biA = inter; buA = uni; miA = gid; }
                }
            }
            {
                float dy = fminf(Bx.z, gb.z) - fmaxf(Bx.x, gb.x);
                float dx = fminf(Bx.w, gb.w) - fmaxf(Bx.y, gb.y);
                if (dy > 0.0f && dx > 0.0f) {
                    float inter = dy * dx;
                    float uni   = (abB + ga) - inter;
                    if (inter * buB > biB * uni) { biB = inter; buB = uni; miB = gid; }
                }
            }
        }
        if (vA) {
            bool posA = (biA > 0.0f) && (__fdiv_rn(biA, buA) >= 0.5f);
            emit(b, iA, posA, miA);
        }
        if (vB) {
            bool posB = (biB > 0.0f) && (__fdiv_rn(biB, buB) >= 0.5f);
            emit(b, iB, posB, miB);
        }
    }
}

// ---------------------------------------------------------------------------
// Kernel 2: per-image select over compacted survivors + 512-sort + gather.
// (round-11 version, verbatim; also resets g_bandcnt) 32 CTAs x 512 threads.
// ---------------------------------------------------------------------------
__global__ __launch_bounds__(512)
void roi_sample_kernel(const float* __restrict__ boxes,
                       const float* __restrict__ gt_boxes,
                       const int*   __restrict__ gt_classes,
                       float* __restrict__ out) {
    extern __shared__ unsigned long long items[];   // KCAP
    __shared__ unsigned hP[KBIN], hN[KBIN], sPc[KBIN], sNc[KBIN];
    __shared__ unsigned wtP[8], wtN[8];
    __shared__ unsigned long long LP[LCAP], LN[LCAP], selk[NSAMP];
    __shared__ unsigned sh_bp, sh_bn, sh_befP, sh_befN;
    __shared__ unsigned cntP, cntN, cntS;
    __shared__ unsigned long long sh_KP, sh_KN;

    const int b = blockIdx.x;
    const int t = threadIdx.x;
    const int T = 512;
    const int lane = t & 31, wid = t >> 5;

    if (t == 0) { cntP = 0; cntN = 0; cntS = 0; sh_KP = MASK37; sh_KN = MASK37; }
    if (t < KBIN) { hP[t] = 0u; hN[t] = 0u; }
    const unsigned M0 = g_cnt[b];
    const unsigned M = (M0 < KCAP) ? M0 : KCAP;
    __syncthreads();
    if (t == 0) g_cnt[b] = 0u;          // reset for next replay
    if (t >= 32 && t < 40) g_bandcnt[b * 8 + (t - 32)] = 0u;

    // load survivors + histogram on inv_m[22:15]  (bits 29..36 of w)
    for (unsigned p = t; p < M; p += T) {
        unsigned long long w = g_sel[b * KCAP + p];
        items[p] = w;
        unsigned bin = (unsigned)(w >> 29) & 0xFFu;
        if ((w >> 37) & 1ull) atomicAdd(&hP[bin], 1u);
        else                  atomicAdd(&hN[bin], 1u);
    }
    __syncthreads();

    // inclusive scan of 256 bins: warp shuffles + tiny cross-warp combine
    unsigned sP = 0, sN = 0;
    if (t < KBIN) {
        sP = hP[t]; sN = hN[t];
#pragma unroll
        for (int off = 1; off < 32; off <<= 1) {
            unsigned vP = __shfl_up_sync(0xFFFFFFFFu, sP, off);
            unsigned vN = __shfl_up_sync(0xFFFFFFFFu, sN, off);
            if (lane >= off) { sP += vP; sN += vN; }
        }
        if (lane == 31) { wtP[wid] = sP; wtN[wid] = sN; }
    }
    __syncthreads();
    if (t < KBIN) {
        unsigned offP = 0, offN = 0;
        for (int ww = 0; ww < wid; ++ww) { offP += wtP[ww]; offN += wtN[ww]; }
        sPc[t] = sP + offP; sNc[t] = sN + offN;
    }
    __syncthreads();

    const unsigned total_pos = sPc[KBIN - 1];
    const unsigned n_pos = (total_pos < (unsigned)NFG) ? total_pos : (unsigned)NFG;
    const unsigned quota = (unsigned)NSAMP - n_pos;
    const bool needPsel = (total_pos > (unsigned)NFG);

    // boundary bins
    if (t < KBIN) {
        unsigned iP = sPc[t], pP = t ? sPc[t - 1] : 0u;
        unsigned iN = sNc[t], pN = t ? sNc[t - 1] : 0u;
        if (needPsel && iP >= (unsigned)NFG && pP < (unsigned)NFG) { sh_bp = (unsigned)t; sh_befP = pP; }
        if (iN >= quota && pN < quota) { sh_bn = (unsigned)t; sh_befN = pN; }
    }
    __syncthreads();

    // collect boundary-bin items (masked 37-bit keys)
    {
        unsigned bp = needPsel ? sh_bp : 0xFFFFFFFFu;
        unsigned bn = sh_bn;
        for (unsigned p = t; p < M; p += T) {
            unsigned long long w = items[p];
            unsigned bin = (unsigned)(w >> 29) & 0xFFu;
            if ((w >> 37) & 1ull) {
                if (bin == bp) { unsigned j = atomicAdd(&cntP, 1u); if (j < LCAP) LP[j] = w & MASK37; }
            } else {
                if (bin == bn) { unsigned j = atomicAdd(&cntN, 1u); if (j < LCAP) LN[j] = w & MASK37; }
            }
        }
    }
    selk[t] = ~0ull;
    __syncthreads();

    // exact rank within boundary bins -> cutoff keys (keys are unique)
    {
        unsigned cp = cntP < LCAP ? cntP : LCAP;
        unsigned cn = cntN < LCAP ? cntN : LCAP;
        if (needPsel && (unsigned)t < cp) {
            unsigned long long k = LP[t]; unsigned r = 0;
            for (unsigned l = 0; l < cp; ++l) r += (LP[l] < k);
            if (r == ((unsigned)NFG - sh_befP) - 1u) sh_KP = k;
        }
        if ((unsigned)t < cn) {
            unsigned long long k = LN[t]; unsigned r = 0;
            for (unsigned l = 0; l < cn; ++l) r += (LN[l] < k);
            if (r == (quota - sh_befN) - 1u) sh_KN = k;
        }
    }
    __syncthreads();

    // final selection (exactly 512); re-key by RNE-rounded score mantissa.
    // score = 2.0f + r rounds r's 23-bit mantissa m to 2^-22 grid:
    //   h = (m>>1) + ((m&1) & ((m>>1)&1)); ties broken by idx asc.
    {
        unsigned long long KP = sh_KP, KN = sh_KN;
        for (unsigned p = t; p < M; p += T) {
            unsigned long long w = items[p];
            unsigned long long kk = w & MASK37;
            bool sel = ((w >> 37) & 1ull) ? (kk <= KP) : (kk <= KN);
            if (sel) {
                unsigned mm = 0x7FFFFFu - (unsigned)((w >> 14) & 0x7FFFFFu);
                unsigned h  = (mm >> 1) + ((mm & 1u) & ((mm >> 1) & 1u));
                unsigned j  = atomicAdd(&cntS, 1u);
                selk[j] = (w & ~MASK37)                        // keep pos|mi high bits
                        | (((unsigned long long)(0x7FFFFFu - h)) << 14)
                        | (w & 0x3FFFull);
            }
        }
    }
    __syncthreads();

    // bitonic sort 512 keys by low 37 bits asc (== score desc, idx asc);
    // pos/mi ride in the high bits, masked out of comparisons via <<27.
    for (unsigned k = 2; k <= (unsigned)NSAMP; k <<= 1) {
        for (unsigned j = k >> 1; j > 0; j >>= 1) {
            unsigned p = (unsigned)t, q = p ^ j;
            if (q > p) {
                unsigned long long a = selk[p], c = selk[q];
                bool up = ((p & k) == 0);
                if (((a << 27) > (c << 27)) == up) { selk[p] = c; selk[q] = a; }
            }
            __syncthreads();
        }
    }

    // gather outputs
    {
        unsigned long long v = selk[t];
        if ((unsigned)t < cntS) {
            unsigned i  = (unsigned)(v & 0x3FFFu);
            bool pos    = (v >> 37) & 1ull;
            int  mi     = (int)((v >> 38) & 0xFFull);
            float4 roi = (i < NBOX)
                ? ((const float4*)boxes)[b * NBOX + i]
                : ((const float4*)gt_boxes)[b * MGT + (i - NBOX)];
            float4 gb = make_float4(0.f, 0.f, 0.f, 0.f);
            float cls = 0.0f, gidx = -1.0f;
            if (pos) {
                gb   = ((const float4*)gt_boxes)[b * MGT + mi];
                cls  = (float)gt_classes[b * MGT + mi];
                gidx = (float)mi;
            }
            size_t base = (size_t)(b * NSAMP + t);
            float* o1 = out + base * 4;                                   // rois
            o1[0] = roi.x; o1[1] = roi.y; o1[2] = roi.z; o1[3] = roi.w;
            float* o2 = out + (size_t)BB * NSAMP * 4 + base * 4;          // matched gt boxes
            o2[0] = gb.x; o2[1] = gb.y; o2[2] = gb.z; o2[3] = gb.w;
            out[(size_t)2 * BB * NSAMP * 4 + base] = cls;                 // classes
            out[(size_t)2 * BB * NSAMP * 4 + (size_t)BB * NSAMP + base] = gidx; // indices
        }
    }
}

extern "C" void kernel_launch(void* const* d_in, const int* in_sizes, int n_in,
                              void* d_out, int out_size) {
    (void)out_size;
    const float* boxes      = (const float*)d_in[0];
    const float* gt_boxes   = (const float*)d_in[1];
    const int*   gt_classes = (const int*)d_in[2];
    for (int k = 0; k < n_in; ++k) {
        if (in_sizes[k] == BB * NBOX * 4) boxes      = (const float*)d_in[k];
        else if (in_sizes[k] == BB * MGT * 4) gt_boxes = (const float*)d_in[k];
        else if (in_sizes[k] == BB * MGT)     gt_classes = (const int*)d_in[k];
    }
    float* out = (float*)d_out;

    dim3 g0(NBOX / 256, BB);
    roi_bin_kernel<<<g0, 256>>>(boxes);

    dim3 g1(BB, 17);
    roi_match_kernel<<<g1, 256>>>(boxes, gt_boxes);

    size_t smem = (size_t)KCAP * 8;   // 32 KB dynamic (items)
    cudaFuncSetAttribute(roi_sample_kernel,
                         cudaFuncAttributeMaxDynamicSharedMemorySize, (int)smem);
    roi_sample_kernel<<<BB, 512, smem>>>(boxes, gt_boxes, gt_classes, out);
}